// round 4
// baseline (speedup 1.0000x reference)
#include <cuda_runtime.h>
#include <cuda_bf16.h>

#define NN 4096
#define DIN 512
#define DH1 256
#define DH2 64
#define ALPHA 0.2f

// packed fp32x2 helpers (Blackwell FFMA2 path)
#define FMA2(d, a, b) asm("fma.rn.f32x2 %0, %1, %2, %0;" : "+l"(d) : "l"(a), "l"(b))
#define BPACK(d, s)   asm("mov.b64 %0, {%1, %1};" : "=l"(d) : "r"(__float_as_uint(s)))
#define UNPK(lo, hi, v) asm("mov.b64 {%0, %1}, %2;" : "=r"(lo), "=r"(hi) : "l"(v))

// ---------------- device scratch (no allocations allowed) ----------------
__device__ float    g_h0[NN * DH1];
__device__ float    g_hidden[NN * DH1];
__device__ float    g_h1[NN * DH2];
__device__ float    g_h2[NN * DH2];
__device__ float    g_mean[NN * DH2];
__device__ float    g_logstd[NN * DH2];
__device__ float    g_Z[NN * DH2];
__device__ float4   g_rowvals[NN];
__device__ float4   g_colvals[NN];
__device__ unsigned g_adjbits[NN * (NN / 32)];
__device__ float    g_pacc[8 * NN * DH1];   // 32 MB: max of 8*N*256 and 16*N*64
__device__ float    g_pden[16 * NN];

// ---------------- pack adjacency into bitmask (2 MB, L2-resident) --------
__global__ void pack_adj_kernel(const int* __restrict__ adj, unsigned* __restrict__ bits) {
    int idx = blockIdx.x * 256 + threadIdx.x;          // one thread per adj element
    unsigned b = __ballot_sync(0xffffffffu, adj[idx] > 0);
    if ((threadIdx.x & 31) == 0) bits[idx >> 5] = b;
}

// ---------------- generic tiled fp32 GEMM: C[M,Nc] = A[M,K] @ B[K,Nc] ----
__global__ __launch_bounds__(256) void gemm64_kernel(
    const float* __restrict__ A, const float* __restrict__ B, float* __restrict__ C,
    int M, int K, int Nc)
{
    __shared__ float As[16][68];
    __shared__ float Bs[16][68];
    const int tid = threadIdx.x;
    const int tx = tid & 15, ty = tid >> 4;
    const int m0 = blockIdx.y * 64, n0 = blockIdx.x * 64;
    const int am = tid >> 2;
    const int ak = (tid & 3) * 4;
    const int bk = tid >> 4;
    const int bn = (tid & 15) * 4;

    float acc[4][4] = {};
    for (int k0 = 0; k0 < K; k0 += 16) {
        float4 av = *(const float4*)&A[(size_t)(m0 + am) * K + k0 + ak];
        float4 bv = *(const float4*)&B[(size_t)(k0 + bk) * Nc + n0 + bn];
        __syncthreads();
        As[ak + 0][am] = av.x; As[ak + 1][am] = av.y;
        As[ak + 2][am] = av.z; As[ak + 3][am] = av.w;
        *(float4*)&Bs[bk][bn] = bv;
        __syncthreads();
#pragma unroll
        for (int k = 0; k < 16; ++k) {
            float4 a4 = *(float4*)&As[k][ty * 4];
            float4 b4 = *(float4*)&Bs[k][tx * 4];
            acc[0][0] += a4.x * b4.x; acc[0][1] += a4.x * b4.y; acc[0][2] += a4.x * b4.z; acc[0][3] += a4.x * b4.w;
            acc[1][0] += a4.y * b4.x; acc[1][1] += a4.y * b4.y; acc[1][2] += a4.y * b4.z; acc[1][3] += a4.y * b4.w;
            acc[2][0] += a4.z * b4.x; acc[2][1] += a4.z * b4.y; acc[2][2] += a4.z * b4.z; acc[2][3] += a4.z * b4.w;
            acc[3][0] += a4.w * b4.x; acc[3][1] += a4.w * b4.y; acc[3][2] += a4.w * b4.z; acc[3][3] += a4.w * b4.w;
        }
    }
#pragma unroll
    for (int i = 0; i < 4; ++i) {
        float4 v = make_float4(acc[i][0], acc[i][1], acc[i][2], acc[i][3]);
        *(float4*)&C[(size_t)(m0 + ty * 4 + i) * Nc + n0 + tx * 4] = v;
    }
}

// ---------------- per-row attention scalars: f1,f2 and their exps --------
// rowvals[i] = (-f1, exp(f1), exp(a*f1), 0); colvals[j] = (f2, exp(f2), exp(a*f2), 0)
__global__ void vals_kernel(const float* __restrict__ h, const float* __restrict__ a,
                            int D, float4* __restrict__ rowvals, float4* __restrict__ colvals)
{
    int warp = (blockIdx.x * blockDim.x + threadIdx.x) >> 5;
    int lane = threadIdx.x & 31;
    if (warp >= NN) return;
    float s1 = 0.f, s2 = 0.f;
    for (int d = lane; d < D; d += 32) {
        float hv = h[(size_t)warp * D + d];
        s1 += hv * a[d];
        s2 += hv * a[D + d];
    }
#pragma unroll
    for (int o = 16; o; o >>= 1) {
        s1 += __shfl_xor_sync(0xffffffffu, s1, o);
        s2 += __shfl_xor_sync(0xffffffffu, s2, o);
    }
    if (lane == 0) {
        rowvals[warp] = make_float4(-s1, expf(s1), expf(ALPHA * s1), 0.f);
        colvals[warp] = make_float4(s2, expf(s2), expf(ALPHA * s2), 0.f);
    }
}

// ---------------- fused masked-softmax attention v2 ----------------------
// Phase A: materialize weight tile W[BJ][BI] in smem (each weight computed once)
//          + per-row denominator partial sums.
// Phase B: pure smem GEMM with packed f32x2 FMA (FFMA2).
template<int D, int TI, int TC, int RPT, int CPT>
__global__ __launch_bounds__(128) void attn2_kernel(
    const float* __restrict__ h,
    const float4* __restrict__ rowvals,
    const float4* __restrict__ colvals,
    const unsigned* __restrict__ adjbits,
    float* __restrict__ pacc,
    float* __restrict__ pden)
{
    constexpr int BI = TI * RPT;         // rows per block
    constexpr int BJ = 32;               // j-tile (one mask word)
    constexpr int PPR = 128 / BI;        // threads covering one row in phase A

    __shared__ __align__(16) float  hs[BJ * D];
    __shared__ __align__(16) float  Ws[BJ * BI];
    __shared__ __align__(16) float4 rvs[BI];
    __shared__ __align__(16) float4 cvs[BJ];
    __shared__ unsigned msw[BI];
    __shared__ float dpar[128];
    __shared__ float den_s[BI];

    const int tid = threadIdx.x;
    const int tc = tid / TI;
    const int ti = tid % TI;
    const int rowbase = blockIdx.x * BI;
    const int split = blockIdx.y;
    const int nsplit = gridDim.y;
    const int jcnt = NN / nsplit;
    const int jbeg = split * jcnt;

    if (tid < BI) {
        rvs[tid] = rowvals[rowbase + tid];
        den_s[tid] = 0.f;
    }

    unsigned long long acc2[RPT][CPT / 2];
#pragma unroll
    for (int r = 0; r < RPT; ++r)
#pragma unroll
        for (int c = 0; c < CPT / 2; ++c) acc2[r][c] = 0ULL;

    const int iA = tid & (BI - 1);
    const int jA0 = tid / BI;

    for (int jt = 0; jt < jcnt; jt += BJ) {
        const int j0 = jbeg + jt;
        __syncthreads();
        // ---- tile loads ----
        const float4* src = (const float4*)(h + (size_t)j0 * D);
        float4* dst = (float4*)hs;
#pragma unroll
        for (int it = 0; it < BJ * D / (4 * 128); ++it)
            dst[tid + it * 128] = src[tid + it * 128];
        if (tid < BJ) cvs[tid] = colvals[j0 + tid];
        if (tid < BI) msw[tid] = adjbits[(size_t)(rowbase + tid) * (NN / 32) + (j0 >> 5)];
        __syncthreads();

        // ---- phase A: weights + denominator partials ----
        {
            float4 rv = rvs[iA];
            unsigned m = msw[iA];
            float dloc = 0.f;
#pragma unroll
            for (int e = 0; e < BI * BJ / 128; ++e) {
                int j = jA0 + PPR * e;
                float4 c = cvs[j];
                bool p = c.x > rv.x;                    // f1_i + f2_j > 0
                float w = p ? (rv.y * c.y) : (rv.z * c.z);
                w = ((m >> j) & 1u) ? w : 0.f;
                Ws[j * BI + iA] = w;
                dloc += w;
            }
            dpar[tid] = dloc;
        }
        __syncthreads();
        if (tid < BI) {
            float s = dpar[tid];
            if (PPR == 2) s += dpar[tid + BI];
            den_s[tid] += s;
        }

        // ---- phase B: packed-FMA GEMM ----
#pragma unroll 2
        for (int j = 0; j < BJ; ++j) {
            const float* wrow = Ws + j * BI + ti;
            unsigned long long w2[RPT];
#pragma unroll
            for (int r = 0; r < RPT; ++r) {
                float w = wrow[r * TI];
                BPACK(w2[r], w);
            }
            const ulonglong2* hp = (const ulonglong2*)(hs + j * D + tc * CPT);
#pragma unroll
            for (int c2 = 0; c2 < CPT / 4; ++c2) {
                ulonglong2 v = hp[c2];
#pragma unroll
                for (int r = 0; r < RPT; ++r) {
                    FMA2(acc2[r][2 * c2 + 0], w2[r], v.x);
                    FMA2(acc2[r][2 * c2 + 1], w2[r], v.y);
                }
            }
        }
    }

    // ---- epilogue ----
#pragma unroll
    for (int r = 0; r < RPT; ++r) {
        int row = rowbase + ti + r * TI;
        float* pa = pacc + ((size_t)split * NN + row) * D + tc * CPT;
#pragma unroll
        for (int c4 = 0; c4 < CPT / 4; ++c4) {
            unsigned l0, h0, l1, h1;
            UNPK(l0, h0, acc2[r][2 * c4 + 0]);
            UNPK(l1, h1, acc2[r][2 * c4 + 1]);
            float4 o = make_float4(__uint_as_float(l0), __uint_as_float(h0),
                                   __uint_as_float(l1), __uint_as_float(h1));
            ((float4*)pa)[c4] = o;
        }
    }
    if (tid < BI) pden[split * NN + rowbase + tid] = den_s[tid];
}

// ---------------- combine split partials + normalize ---------------------
__global__ void combine_kernel(const float* __restrict__ pacc, const float* __restrict__ pden,
                               float* __restrict__ out, int D, int nsplit)
{
    int idx = blockIdx.x * blockDim.x + threadIdx.x;    // float4 index
    int total = NN * D / 4;
    if (idx >= total) return;
    int row = idx / (D / 4);
    float4 s = make_float4(0.f, 0.f, 0.f, 0.f);
    float dd = 0.f;
    for (int sp = 0; sp < nsplit; ++sp) {
        float4 v = ((const float4*)pacc)[(size_t)sp * total + idx];
        s.x += v.x; s.y += v.y; s.z += v.z; s.w += v.w;
        dd += pden[sp * NN + row];
    }
    float inv = 1.f / dd;
    s.x *= inv; s.y *= inv; s.z *= inv; s.w *= inv;
    ((float4*)out)[idx] = s;
}

// ---------------- Z = noise * exp(logstd) + mean -------------------------
__global__ void z_kernel(const float* __restrict__ noise, const float* __restrict__ logstd,
                         const float* __restrict__ mean, float* __restrict__ Z)
{
    int idx = blockIdx.x * blockDim.x + threadIdx.x;
    if (idx >= NN * DH2) return;
    Z[idx] = noise[idx] * expf(logstd[idx]) + mean[idx];
}

// ---------------- A = sigmoid(Z @ Z^T), symmetric, FFMA2 -----------------
__global__ __launch_bounds__(256) void zzt_kernel(const float* __restrict__ Z, float* __restrict__ out)
{
    const int bi = blockIdx.y, bj = blockIdx.x;
    if (bj < bi) return;
    __shared__ __align__(16) float ZiT[64][68];
    __shared__ __align__(16) float ZjT[64][68];
    const int tid = threadIdx.x;
    const int r = tid >> 2;
    const int kq = (tid & 3) * 16;
    const int i0 = bi * 64, j0 = bj * 64;
#pragma unroll
    for (int q = 0; q < 4; ++q) {
        int k = kq + q * 4;
        float4 v = *(const float4*)&Z[(size_t)(i0 + r) * DH2 + k];
        ZiT[k + 0][r] = v.x; ZiT[k + 1][r] = v.y; ZiT[k + 2][r] = v.z; ZiT[k + 3][r] = v.w;
        float4 u = *(const float4*)&Z[(size_t)(j0 + r) * DH2 + k];
        ZjT[k + 0][r] = u.x; ZjT[k + 1][r] = u.y; ZjT[k + 2][r] = u.z; ZjT[k + 3][r] = u.w;
    }
    __syncthreads();
    const int tx = tid & 15, ty = tid >> 4;
    unsigned long long acc2[4][2];
#pragma unroll
    for (int i = 0; i < 4; ++i) { acc2[i][0] = 0ULL; acc2[i][1] = 0ULL; }
#pragma unroll 16
    for (int k = 0; k < 64; ++k) {
        float4 a4 = *(float4*)&ZiT[k][ty * 4];
        ulonglong2 b2 = *(ulonglong2*)&ZjT[k][tx * 4];
        unsigned long long ap[4];
        BPACK(ap[0], a4.x); BPACK(ap[1], a4.y); BPACK(ap[2], a4.z); BPACK(ap[3], a4.w);
#pragma unroll
        for (int i = 0; i < 4; ++i) {
            FMA2(acc2[i][0], ap[i], b2.x);
            FMA2(acc2[i][1], ap[i], b2.y);
        }
    }
    float s[4][4];
#pragma unroll
    for (int i = 0; i < 4; ++i) {
        unsigned l0, h0, l1, h1;
        UNPK(l0, h0, acc2[i][0]);
        UNPK(l1, h1, acc2[i][1]);
        float v0 = __uint_as_float(l0), v1 = __uint_as_float(h0);
        float v2 = __uint_as_float(l1), v3 = __uint_as_float(h1);
        s[i][0] = __fdividef(1.f, 1.f + __expf(-v0));
        s[i][1] = __fdividef(1.f, 1.f + __expf(-v1));
        s[i][2] = __fdividef(1.f, 1.f + __expf(-v2));
        s[i][3] = __fdividef(1.f, 1.f + __expf(-v3));
    }
#pragma unroll
    for (int i = 0; i < 4; ++i) {
        float4 v = make_float4(s[i][0], s[i][1], s[i][2], s[i][3]);
        *(float4*)&out[(size_t)(i0 + ty * 4 + i) * NN + j0 + tx * 4] = v;
    }
    if (bj > bi) {
#pragma unroll
        for (int j = 0; j < 4; ++j) {
            float4 v = make_float4(s[0][j], s[1][j], s[2][j], s[3][j]);
            *(float4*)&out[(size_t)(j0 + tx * 4 + j) * NN + i0 + ty * 4] = v;
        }
    }
}

// ---------------- host orchestration -------------------------------------
extern "C" void kernel_launch(void* const* d_in, const int* in_sizes, int n_in,
                              void* d_out, int out_size)
{
    const float* X     = (const float*)d_in[0];
    const int*   adj   = (const int*)  d_in[1];
    const float* noise = (const float*)d_in[2];
    const float* W0    = (const float*)d_in[3];
    const float* a0    = (const float*)d_in[4];
    const float* W1    = (const float*)d_in[5];
    const float* a1    = (const float*)d_in[6];
    const float* W2    = (const float*)d_in[7];
    const float* a2    = (const float*)d_in[8];
    float* out = (float*)d_out;

    float *p_h0, *p_hidden, *p_h1, *p_h2, *p_mean, *p_logstd, *p_Z, *p_pacc, *p_pden;
    float4 *p_rv, *p_cv;
    unsigned* p_bits;
    cudaGetSymbolAddress((void**)&p_h0, g_h0);
    cudaGetSymbolAddress((void**)&p_hidden, g_hidden);
    cudaGetSymbolAddress((void**)&p_h1, g_h1);
    cudaGetSymbolAddress((void**)&p_h2, g_h2);
    cudaGetSymbolAddress((void**)&p_mean, g_mean);
    cudaGetSymbolAddress((void**)&p_logstd, g_logstd);
    cudaGetSymbolAddress((void**)&p_Z, g_Z);
    cudaGetSymbolAddress((void**)&p_pacc, g_pacc);
    cudaGetSymbolAddress((void**)&p_pden, g_pden);
    cudaGetSymbolAddress((void**)&p_rv, g_rowvals);
    cudaGetSymbolAddress((void**)&p_cv, g_colvals);
    cudaGetSymbolAddress((void**)&p_bits, g_adjbits);

    // adjacency bitmask
    pack_adj_kernel<<<NN * NN / 256, 256>>>(adj, p_bits);

    // ---- layer 0: h0 = X@W0 ; hidden = attn(h0) ----
    gemm64_kernel<<<dim3(DH1 / 64, NN / 64), 256>>>(X, W0, p_h0, NN, DIN, DH1);
    vals_kernel<<<NN / 8, 256>>>(p_h0, a0, DH1, p_rv, p_cv);
    attn2_kernel<DH1, 8, 16, 8, 16><<<dim3(NN / 64, 8), 128>>>(p_h0, p_rv, p_cv, p_bits, p_pacc, p_pden);
    combine_kernel<<<NN * DH1 / 4 / 256, 256>>>(p_pacc, p_pden, p_hidden, DH1, 8);

    // ---- layer 1 (mean) ----
    gemm64_kernel<<<dim3(DH2 / 64, NN / 64), 256>>>(p_hidden, W1, p_h1, NN, DH1, DH2);
    vals_kernel<<<NN / 8, 256>>>(p_h1, a1, DH2, p_rv, p_cv);
    attn2_kernel<DH2, 16, 8, 8, 8><<<dim3(NN / 128, 16), 128>>>(p_h1, p_rv, p_cv, p_bits, p_pacc, p_pden);
    combine_kernel<<<NN * DH2 / 4 / 256, 256>>>(p_pacc, p_pden, p_mean, DH2, 16);

    // ---- layer 2 (logstd) ----
    gemm64_kernel<<<dim3(DH2 / 64, NN / 64), 256>>>(p_hidden, W2, p_h2, NN, DH1, DH2);
    vals_kernel<<<NN / 8, 256>>>(p_h2, a2, DH2, p_rv, p_cv);
    attn2_kernel<DH2, 16, 8, 8, 8><<<dim3(NN / 128, 16), 128>>>(p_h2, p_rv, p_cv, p_bits, p_pacc, p_pden);
    combine_kernel<<<NN * DH2 / 4 / 256, 256>>>(p_pacc, p_pden, p_logstd, DH2, 16);

    // ---- Z and decoder ----
    z_kernel<<<NN * DH2 / 256, 256>>>(noise, p_logstd, p_mean, p_Z);
    zzt_kernel<<<dim3(NN / 64, NN / 64), 256>>>(p_Z, out);
}

// round 5
// speedup vs baseline: 1.6647x; 1.6647x over previous
#include <cuda_runtime.h>
#include <cuda_bf16.h>

#define NN 4096
#define DIN 512
#define DH1 256
#define DH2 64
#define ALPHA 0.2f

// packed fp32x2 helpers (used in zzt)
#define FMA2(d, a, b) asm("fma.rn.f32x2 %0, %1, %2, %0;" : "+l"(d) : "l"(a), "l"(b))
#define BPACK(d, s)   asm("mov.b64 %0, {%1, %1};" : "=l"(d) : "r"(__float_as_uint(s)))
#define UNPK(lo, hi, v) asm("mov.b64 {%0, %1}, %2;" : "=r"(lo), "=r"(hi) : "l"(v))

__device__ __forceinline__ unsigned f2tf(float f) {
    unsigned u; asm("cvt.rna.tf32.f32 %0, %1;" : "=r"(u) : "f"(f)); return u;
}
__device__ __forceinline__ void mma_tf32(float* c, const unsigned* a, unsigned b0, unsigned b1) {
    asm volatile("mma.sync.aligned.m16n8k8.row.col.f32.tf32.tf32.f32 "
                 "{%0,%1,%2,%3}, {%4,%5,%6,%7}, {%8,%9}, {%0,%1,%2,%3};"
                 : "+f"(c[0]), "+f"(c[1]), "+f"(c[2]), "+f"(c[3])
                 : "r"(a[0]), "r"(a[1]), "r"(a[2]), "r"(a[3]), "r"(b0), "r"(b1));
}

// ---------------- device scratch (no allocations allowed) ----------------
__device__ float    g_h0[NN * DH1];
__device__ float    g_hidden[NN * DH1];
__device__ float    g_h1[NN * DH2];
__device__ float    g_h2[NN * DH2];
__device__ float    g_mean[NN * DH2];
__device__ float    g_logstd[NN * DH2];
__device__ float    g_Z[NN * DH2];
__device__ float4   g_rowvals[NN];
__device__ float4   g_colvals[NN];
__device__ unsigned g_adjbits[NN * (NN / 32)];
__device__ float    g_pacc[8 * NN * DH1];
__device__ float    g_pden[16 * NN];

// ---------------- pack adjacency into bitmask (2 MB, L2-resident) --------
__global__ void pack_adj_kernel(const int* __restrict__ adj, unsigned* __restrict__ bits) {
    int idx = blockIdx.x * 256 + threadIdx.x;
    unsigned b = __ballot_sync(0xffffffffu, adj[idx] > 0);
    if ((threadIdx.x & 31) == 0) bits[idx >> 5] = b;
}

// ---------------- generic tiled fp32 GEMM: C[M,Nc] = A[M,K] @ B[K,Nc] ----
__global__ __launch_bounds__(256) void gemm64_kernel(
    const float* __restrict__ A, const float* __restrict__ B, float* __restrict__ C,
    int M, int K, int Nc)
{
    __shared__ float As[16][68];
    __shared__ float Bs[16][68];
    const int tid = threadIdx.x;
    const int tx = tid & 15, ty = tid >> 4;
    const int m0 = blockIdx.y * 64, n0 = blockIdx.x * 64;
    const int am = tid >> 2;
    const int ak = (tid & 3) * 4;
    const int bk = tid >> 4;
    const int bn = (tid & 15) * 4;

    float acc[4][4] = {};
    for (int k0 = 0; k0 < K; k0 += 16) {
        float4 av = *(const float4*)&A[(size_t)(m0 + am) * K + k0 + ak];
        float4 bv = *(const float4*)&B[(size_t)(k0 + bk) * Nc + n0 + bn];
        __syncthreads();
        As[ak + 0][am] = av.x; As[ak + 1][am] = av.y;
        As[ak + 2][am] = av.z; As[ak + 3][am] = av.w;
        *(float4*)&Bs[bk][bn] = bv;
        __syncthreads();
#pragma unroll
        for (int k = 0; k < 16; ++k) {
            float4 a4 = *(float4*)&As[k][ty * 4];
            float4 b4 = *(float4*)&Bs[k][tx * 4];
            acc[0][0] += a4.x * b4.x; acc[0][1] += a4.x * b4.y; acc[0][2] += a4.x * b4.z; acc[0][3] += a4.x * b4.w;
            acc[1][0] += a4.y * b4.x; acc[1][1] += a4.y * b4.y; acc[1][2] += a4.y * b4.z; acc[1][3] += a4.y * b4.w;
            acc[2][0] += a4.z * b4.x; acc[2][1] += a4.z * b4.y; acc[2][2] += a4.z * b4.z; acc[2][3] += a4.z * b4.w;
            acc[3][0] += a4.w * b4.x; acc[3][1] += a4.w * b4.y; acc[3][2] += a4.w * b4.z; acc[3][3] += a4.w * b4.w;
        }
    }
#pragma unroll
    for (int i = 0; i < 4; ++i) {
        float4 v = make_float4(acc[i][0], acc[i][1], acc[i][2], acc[i][3]);
        *(float4*)&C[(size_t)(m0 + ty * 4 + i) * Nc + n0 + tx * 4] = v;
    }
}

// ---------------- per-row attention scalars ------------------------------
__global__ void vals_kernel(const float* __restrict__ h, const float* __restrict__ a,
                            int D, float4* __restrict__ rowvals, float4* __restrict__ colvals)
{
    int warp = (blockIdx.x * blockDim.x + threadIdx.x) >> 5;
    int lane = threadIdx.x & 31;
    if (warp >= NN) return;
    float s1 = 0.f, s2 = 0.f;
    for (int d = lane; d < D; d += 32) {
        float hv = h[(size_t)warp * D + d];
        s1 += hv * a[d];
        s2 += hv * a[D + d];
    }
#pragma unroll
    for (int o = 16; o; o >>= 1) {
        s1 += __shfl_xor_sync(0xffffffffu, s1, o);
        s2 += __shfl_xor_sync(0xffffffffu, s2, o);
    }
    if (lane == 0) {
        rowvals[warp] = make_float4(-s1, expf(s1), expf(ALPHA * s1), 0.f);
        colvals[warp] = make_float4(s2, expf(s2), expf(ALPHA * s2), 0.f);
    }
}

// ---------------- attention v3: weight tile + tf32 mma.sync --------------
// Phase A: compute W[BJ=32][BI=128] tile (tf32 in smem) + fp32 denominators.
// Phase B: tf32 mma.sync GEMM: out[BI, DC] += W^T @ h_tile[BJ, DC].
// Layouts: Ws[k][i] with BIp=136 pad; hs[k][n] with DCp=DC+8 pad (conflict-free).
template<int D, int DC, int MT, int ROWG, int COLG>
__global__ __launch_bounds__(256) void attn3_kernel(
    const float* __restrict__ h,
    const float4* __restrict__ rowvals,
    const float4* __restrict__ colvals,
    const unsigned* __restrict__ adjbits,
    float* __restrict__ pacc,
    float* __restrict__ pden)
{
    constexpr int BI = 128;
    constexpr int BJ = 32;
    constexpr int BIp = 136;
    constexpr int DCp = DC + 8;
    constexpr int NT = DC / COLG / 8;       // n-tiles per warp (8)

    __shared__ __align__(16) unsigned Ws[BJ * BIp];
    __shared__ __align__(16) unsigned hs[BJ * DCp];
    __shared__ __align__(16) float4 rvs[BI];
    __shared__ __align__(16) float4 cvs[BJ];
    __shared__ unsigned msw[BI];
    __shared__ float dpar[256];
    __shared__ float den_s[BI];

    const int tid = threadIdx.x;
    const int wid = tid >> 5;
    const int lane = tid & 31;
    const int grp = lane >> 2;              // 0..7
    const int tid4 = lane & 3;              // 0..3
    const int warpRow = wid % ROWG;
    const int warpCol = wid / ROWG;
    const int rowbase = blockIdx.x * BI;
    const int colbase = blockIdx.y * DC;
    const int split = blockIdx.z;
    const int jcnt = NN / gridDim.z;
    const int jbeg = split * jcnt;

    if (tid < BI) {
        rvs[tid] = rowvals[rowbase + tid];
        den_s[tid] = 0.f;
    }

    float acc[MT][NT][4];
#pragma unroll
    for (int m = 0; m < MT; ++m)
#pragma unroll
        for (int n = 0; n < NT; ++n)
#pragma unroll
            for (int q = 0; q < 4; ++q) acc[m][n][q] = 0.f;

    const int iA = tid & (BI - 1);
    const int jAb = (tid >> 7) * 16;

    for (int jt = 0; jt < jcnt; jt += BJ) {
        const int j0 = jbeg + jt;
        __syncthreads();
        // ---- load h tile -> tf32 smem ----
#pragma unroll
        for (int it = 0; it < BJ * DC / (4 * 256); ++it) {
            int q = tid + it * 256;
            int row = q / (DC / 4);
            int c4 = (q % (DC / 4)) * 4;
            float4 v = *(const float4*)&h[(size_t)(j0 + row) * D + colbase + c4];
            uint4 t;
            t.x = f2tf(v.x); t.y = f2tf(v.y); t.z = f2tf(v.z); t.w = f2tf(v.w);
            *(uint4*)&hs[row * DCp + c4] = t;
        }
        if (tid < BJ) cvs[tid] = colvals[j0 + tid];
        if (tid < BI) msw[tid] = adjbits[(size_t)(rowbase + tid) * (NN / 32) + (j0 >> 5)];
        __syncthreads();

        // ---- phase A: weights (once per pair) + denominator partials ----
        {
            float4 rv = rvs[iA];
            unsigned m = msw[iA];
            float dloc = 0.f;
#pragma unroll
            for (int e = 0; e < 16; ++e) {
                int j = jAb + e;
                float4 c = cvs[j];
                bool p = c.x > rv.x;
                float w = p ? (rv.y * c.y) : (rv.z * c.z);
                w = ((m >> j) & 1u) ? w : 0.f;
                Ws[j * BIp + iA] = f2tf(w);
                dloc += w;
            }
            dpar[tid] = dloc;
        }
        __syncthreads();
        if (tid < BI) den_s[tid] += dpar[tid] + dpar[tid + BI];

        // ---- phase B: tf32 mma GEMM ----
#pragma unroll
        for (int k0 = 0; k0 < BJ; k0 += 8) {
            unsigned afr[MT][4];
#pragma unroll
            for (int m = 0; m < MT; ++m) {
                int rb = (warpRow * MT + m) * 16;
                afr[m][0] = Ws[(k0 + tid4) * BIp + rb + grp];
                afr[m][1] = Ws[(k0 + tid4) * BIp + rb + grp + 8];
                afr[m][2] = Ws[(k0 + tid4 + 4) * BIp + rb + grp];
                afr[m][3] = Ws[(k0 + tid4 + 4) * BIp + rb + grp + 8];
            }
#pragma unroll
            for (int n = 0; n < NT; ++n) {
                int n0 = warpCol * (NT * 8) + n * 8;
                unsigned b0 = hs[(k0 + tid4) * DCp + n0 + grp];
                unsigned b1 = hs[(k0 + tid4 + 4) * DCp + n0 + grp];
#pragma unroll
                for (int m = 0; m < MT; ++m)
                    mma_tf32(acc[m][n], afr[m], b0, b1);
            }
        }
    }

    // ---- epilogue: write partial accumulators ----
#pragma unroll
    for (int m = 0; m < MT; ++m) {
        int r0 = rowbase + (warpRow * MT + m) * 16 + grp;
#pragma unroll
        for (int n = 0; n < NT; ++n) {
            int col = colbase + warpCol * (NT * 8) + n * 8 + 2 * tid4;
            float* p0 = pacc + ((size_t)split * NN + r0) * D + col;
            float* p1 = pacc + ((size_t)split * NN + r0 + 8) * D + col;
            *(float2*)p0 = make_float2(acc[m][n][0], acc[m][n][1]);
            *(float2*)p1 = make_float2(acc[m][n][2], acc[m][n][3]);
        }
    }
    if (blockIdx.y == 0 && tid < BI) pden[split * NN + rowbase + tid] = den_s[tid];
}

// ---------------- combine split partials + normalize ---------------------
__global__ void combine_kernel(const float* __restrict__ pacc, const float* __restrict__ pden,
                               float* __restrict__ out, int D, int nsplit)
{
    int idx = blockIdx.x * blockDim.x + threadIdx.x;
    int total = NN * D / 4;
    if (idx >= total) return;
    int row = idx / (D / 4);
    float4 s = make_float4(0.f, 0.f, 0.f, 0.f);
    float dd = 0.f;
    for (int sp = 0; sp < nsplit; ++sp) {
        float4 v = ((const float4*)pacc)[(size_t)sp * total + idx];
        s.x += v.x; s.y += v.y; s.z += v.z; s.w += v.w;
        dd += pden[sp * NN + row];
    }
    float inv = 1.f / dd;
    s.x *= inv; s.y *= inv; s.z *= inv; s.w *= inv;
    ((float4*)out)[idx] = s;
}

// ---------------- Z = noise * exp(logstd) + mean -------------------------
__global__ void z_kernel(const float* __restrict__ noise, const float* __restrict__ logstd,
                         const float* __restrict__ mean, float* __restrict__ Z)
{
    int idx = blockIdx.x * blockDim.x + threadIdx.x;
    if (idx >= NN * DH2) return;
    Z[idx] = noise[idx] * expf(logstd[idx]) + mean[idx];
}

// ---------------- A = sigmoid(Z @ Z^T), symmetric, FFMA2 -----------------
__global__ __launch_bounds__(256) void zzt_kernel(const float* __restrict__ Z, float* __restrict__ out)
{
    const int bi = blockIdx.y, bj = blockIdx.x;
    if (bj < bi) return;
    __shared__ __align__(16) float ZiT[64][68];
    __shared__ __align__(16) float ZjT[64][68];
    const int tid = threadIdx.x;
    const int r = tid >> 2;
    const int kq = (tid & 3) * 16;
    const int i0 = bi * 64, j0 = bj * 64;
#pragma unroll
    for (int q = 0; q < 4; ++q) {
        int k = kq + q * 4;
        float4 v = *(const float4*)&Z[(size_t)(i0 + r) * DH2 + k];
        ZiT[k + 0][r] = v.x; ZiT[k + 1][r] = v.y; ZiT[k + 2][r] = v.z; ZiT[k + 3][r] = v.w;
        float4 u = *(const float4*)&Z[(size_t)(j0 + r) * DH2 + k];
        ZjT[k + 0][r] = u.x; ZjT[k + 1][r] = u.y; ZjT[k + 2][r] = u.z; ZjT[k + 3][r] = u.w;
    }
    __syncthreads();
    const int tx = tid & 15, ty = tid >> 4;
    unsigned long long acc2[4][2];
#pragma unroll
    for (int i = 0; i < 4; ++i) { acc2[i][0] = 0ULL; acc2[i][1] = 0ULL; }
#pragma unroll 16
    for (int k = 0; k < 64; ++k) {
        float4 a4 = *(float4*)&ZiT[k][ty * 4];
        ulonglong2 b2 = *(ulonglong2*)&ZjT[k][tx * 4];
        unsigned long long ap[4];
        BPACK(ap[0], a4.x); BPACK(ap[1], a4.y); BPACK(ap[2], a4.z); BPACK(ap[3], a4.w);
#pragma unroll
        for (int i = 0; i < 4; ++i) {
            FMA2(acc2[i][0], ap[i], b2.x);
            FMA2(acc2[i][1], ap[i], b2.y);
        }
    }
    float s[4][4];
#pragma unroll
    for (int i = 0; i < 4; ++i) {
        unsigned l0, h0, l1, h1;
        UNPK(l0, h0, acc2[i][0]);
        UNPK(l1, h1, acc2[i][1]);
        s[i][0] = __fdividef(1.f, 1.f + __expf(-__uint_as_float(l0)));
        s[i][1] = __fdividef(1.f, 1.f + __expf(-__uint_as_float(h0)));
        s[i][2] = __fdividef(1.f, 1.f + __expf(-__uint_as_float(l1)));
        s[i][3] = __fdividef(1.f, 1.f + __expf(-__uint_as_float(h1)));
    }
#pragma unroll
    for (int i = 0; i < 4; ++i) {
        float4 v = make_float4(s[i][0], s[i][1], s[i][2], s[i][3]);
        *(float4*)&out[(size_t)(i0 + ty * 4 + i) * NN + j0 + tx * 4] = v;
    }
    if (bj > bi) {
#pragma unroll
        for (int j = 0; j < 4; ++j) {
            float4 v = make_float4(s[0][j], s[1][j], s[2][j], s[3][j]);
            *(float4*)&out[(size_t)(j0 + tx * 4 + j) * NN + i0 + ty * 4] = v;
        }
    }
}

// ---------------- host orchestration -------------------------------------
extern "C" void kernel_launch(void* const* d_in, const int* in_sizes, int n_in,
                              void* d_out, int out_size)
{
    const float* X     = (const float*)d_in[0];
    const int*   adj   = (const int*)  d_in[1];
    const float* noise = (const float*)d_in[2];
    const float* W0    = (const float*)d_in[3];
    const float* a0    = (const float*)d_in[4];
    const float* W1    = (const float*)d_in[5];
    const float* a1    = (const float*)d_in[6];
    const float* W2    = (const float*)d_in[7];
    const float* a2    = (const float*)d_in[8];
    float* out = (float*)d_out;

    float *p_h0, *p_hidden, *p_h1, *p_h2, *p_mean, *p_logstd, *p_Z, *p_pacc, *p_pden;
    float4 *p_rv, *p_cv;
    unsigned* p_bits;
    cudaGetSymbolAddress((void**)&p_h0, g_h0);
    cudaGetSymbolAddress((void**)&p_hidden, g_hidden);
    cudaGetSymbolAddress((void**)&p_h1, g_h1);
    cudaGetSymbolAddress((void**)&p_h2, g_h2);
    cudaGetSymbolAddress((void**)&p_mean, g_mean);
    cudaGetSymbolAddress((void**)&p_logstd, g_logstd);
    cudaGetSymbolAddress((void**)&p_Z, g_Z);
    cudaGetSymbolAddress((void**)&p_pacc, g_pacc);
    cudaGetSymbolAddress((void**)&p_pden, g_pden);
    cudaGetSymbolAddress((void**)&p_rv, g_rowvals);
    cudaGetSymbolAddress((void**)&p_cv, g_colvals);
    cudaGetSymbolAddress((void**)&p_bits, g_adjbits);

    // adjacency bitmask
    pack_adj_kernel<<<NN * NN / 256, 256>>>(adj, p_bits);

    // ---- layer 0: h0 = X@W0 ; hidden = attn(h0) ----
    gemm64_kernel<<<dim3(DH1 / 64, NN / 64), 256>>>(X, W0, p_h0, NN, DIN, DH1);
    vals_kernel<<<NN / 8, 256>>>(p_h0, a0, DH1, p_rv, p_cv);
    // D=256, DC=128, MT=2, ROWG=4, COLG=2; grid (rows, colblocks, splits)
    attn3_kernel<DH1, 128, 2, 4, 2><<<dim3(NN / 128, 2, 4), 256>>>(p_h0, p_rv, p_cv, p_bits, p_pacc, p_pden);
    combine_kernel<<<NN * DH1 / 4 / 256, 256>>>(p_pacc, p_pden, p_hidden, DH1, 4);

    // ---- layer 1 (mean) ----
    gemm64_kernel<<<dim3(DH2 / 64, NN / 64), 256>>>(p_hidden, W1, p_h1, NN, DH1, DH2);
    vals_kernel<<<NN / 8, 256>>>(p_h1, a1, DH2, p_rv, p_cv);
    attn3_kernel<DH2, 64, 1, 8, 1><<<dim3(NN / 128, 1, 8), 256>>>(p_h1, p_rv, p_cv, p_bits, p_pacc, p_pden);
    combine_kernel<<<NN * DH2 / 4 / 256, 256>>>(p_pacc, p_pden, p_mean, DH2, 8);

    // ---- layer 2 (logstd) ----
    gemm64_kernel<<<dim3(DH2 / 64, NN / 64), 256>>>(p_hidden, W2, p_h2, NN, DH1, DH2);
    vals_kernel<<<NN / 8, 256>>>(p_h2, a2, DH2, p_rv, p_cv);
    attn3_kernel<DH2, 64, 1, 8, 1><<<dim3(NN / 128, 1, 8), 256>>>(p_h2, p_rv, p_cv, p_bits, p_pacc, p_pden);
    combine_kernel<<<NN * DH2 / 4 / 256, 256>>>(p_pacc, p_pden, p_logstd, DH2, 8);

    // ---- Z and decoder ----
    z_kernel<<<NN * DH2 / 256, 256>>>(noise, p_logstd, p_mean, p_Z);
    zzt_kernel<<<dim3(NN / 64, NN / 64), 256>>>(p_Z, out);
}